// round 2
// baseline (speedup 1.0000x reference)
#include <cuda_runtime.h>
#include <cuda_bf16.h>
#include <cstdint>

// GCNConv forward:
//   out[i] = dis[i] * ( sum_{(r->i) in E} dis[r]*xw[r] + dis[i]*xw[i] ) + b
// where xw = x @ W, dis = rsqrt(deg), deg[i] = 1 (self loop) + #edges into i.
//
// Inputs (metadata order): x[f32 N*64], edge_index[INT32 2*E] (jax downcasts
// int64->int32 without x64 mode), W[f32 64*64], b[f32 64]. Output: f32 N*64.

#define MAXN 100000
#define D 64

__device__ float  g_deg[MAXN];
__device__ float4 g_sxw4[(size_t)MAXN * (D / 4)];   // dis[r]*(x@W)[r], 16B aligned

// ---------------------------------------------------------------------------
// K0: zero the output accumulator (d_out) and init deg to 1.0 (self loop)
// ---------------------------------------------------------------------------
__global__ void k0_init(float4* __restrict__ out4, int n)
{
    int t = blockIdx.x * blockDim.x + threadIdx.x;
    int total4 = n * (D / 4);
    if (t < total4) out4[t] = make_float4(0.f, 0.f, 0.f, 0.f);
    if (t < n) g_deg[t] = 1.0f;
}

// ---------------------------------------------------------------------------
// K1: degree accumulation over edge targets (col = edge_index[1][e])
// ---------------------------------------------------------------------------
__global__ void k1_degree(const int* __restrict__ ei, int e_cnt)
{
    int t = blockIdx.x * blockDim.x + threadIdx.x;
    if (t >= e_cnt) return;
    int c = ei[e_cnt + t];
    atomicAdd(&g_deg[c], 1.0f);
}

// ---------------------------------------------------------------------------
// K2: sxw = rsqrt(deg[row]) * (x @ W).  W staged in shared (16 KB),
//     16 rows of x per block (4 KB), 256 threads: thread = (row, 4-col group).
// ---------------------------------------------------------------------------
#define GEMM_ROWS 16
__global__ __launch_bounds__(256) void k2_gemm(const float* __restrict__ x,
                                               const float* __restrict__ W,
                                               int n)
{
    __shared__ float Ws[D * D];
    __shared__ float xs[GEMM_ROWS][D];

    int tid = threadIdx.x;

    // load W (4096 floats = 1024 float4)
    const float4* W4 = (const float4*)W;
    float4* Ws4 = (float4*)Ws;
#pragma unroll
    for (int i = 0; i < 4; i++) Ws4[tid + i * 256] = W4[tid + i * 256];

    int row0 = blockIdx.x * GEMM_ROWS;
    {
        int r = tid >> 4;
        int l = tid & 15;
        int gr = row0 + r;
        float4 v = make_float4(0.f, 0.f, 0.f, 0.f);
        if (gr < n) v = ((const float4*)(x + (size_t)gr * D))[l];
        ((float4*)&xs[r][0])[l] = v;
    }
    __syncthreads();

    int r  = tid >> 4;
    int c4 = (tid & 15) * 4;
    float s0 = 0.f, s1 = 0.f, s2 = 0.f, s3 = 0.f;
#pragma unroll
    for (int k = 0; k < D; k++) {
        float  xv = xs[r][k];
        float4 w  = *(const float4*)(Ws + k * D + c4);
        s0 += xv * w.x; s1 += xv * w.y; s2 += xv * w.z; s3 += xv * w.w;
    }

    int gr = row0 + r;
    if (gr < n) {
        float dis = rsqrtf(g_deg[gr]);
        g_sxw4[(size_t)gr * (D / 4) + (tid & 15)] =
            make_float4(s0 * dis, s1 * dis, s2 * dis, s3 * dis);
    }
}

// ---------------------------------------------------------------------------
// K3: edge scatter — acc(d_out)[col] += sxw[row], 16 threads per edge,
//     one float4 gather + one red.global.add.v4.f32 each.
// ---------------------------------------------------------------------------
__global__ __launch_bounds__(256) void k3_scatter(const int* __restrict__ ei,
                                                  float* __restrict__ acc, int e_cnt)
{
    int t = blockIdx.x * blockDim.x + threadIdx.x;
    int edge = t >> 4;
    if (edge >= e_cnt) return;
    int lane = t & 15;

    int r = ei[edge];
    int c = ei[e_cnt + edge];

    float4 v = g_sxw4[(size_t)r * (D / 4) + lane];
    float* dst = acc + (size_t)c * D + lane * 4;
    asm volatile("red.global.add.v4.f32 [%0], {%1, %2, %3, %4};"
                 :: "l"(dst), "f"(v.x), "f"(v.y), "f"(v.z), "f"(v.w) : "memory");
}

// ---------------------------------------------------------------------------
// K4: finalize — out = dis * (acc + sxw) + b   (in-place on d_out)
// ---------------------------------------------------------------------------
__global__ void k4_final(float* __restrict__ out, const float* __restrict__ b,
                         int n)
{
    int t = blockIdx.x * blockDim.x + threadIdx.x;
    if (t >= n * (D / 4)) return;
    int node = t >> 4;
    int c4 = (t & 15) * 4;

    float dis = rsqrtf(g_deg[node]);
    float4 a = ((float4*)out)[t];
    float4 s = g_sxw4[t];
    float4 bb = *(const float4*)(b + c4);
    float4 o;
    o.x = dis * (a.x + s.x) + bb.x;
    o.y = dis * (a.y + s.y) + bb.y;
    o.z = dis * (a.z + s.z) + bb.z;
    o.w = dis * (a.w + s.w) + bb.w;
    ((float4*)out)[t] = o;
}

// ---------------------------------------------------------------------------
extern "C" void kernel_launch(void* const* d_in, const int* in_sizes, int n_in,
                              void* d_out, int out_size)
{
    const float* x  = (const float*)d_in[0];
    const int*   ei = (const int*)d_in[1];     // int32 (jax default, no x64)
    const float* W  = (const float*)d_in[2];
    const float* b  = (const float*)d_in[3];
    float* out = (float*)d_out;

    int n = in_sizes[0] / D;       // 100000
    int e = in_sizes[1] / 2;       // 1600000

    // K0: zero out + init deg
    {
        int total = n * (D / 4);
        int threads = 256;
        int blocks = (total + threads - 1) / threads;
        k0_init<<<blocks, threads>>>((float4*)out, n);
    }
    // K1: degree scatter
    {
        int threads = 256;
        int blocks = (e + threads - 1) / threads;
        k1_degree<<<blocks, threads>>>(ei, e);
    }
    // K2: sxw = rsqrt(deg) * (x @ W)
    {
        int blocks = (n + GEMM_ROWS - 1) / GEMM_ROWS;
        k2_gemm<<<blocks, 256>>>(x, W, n);
    }
    // K3: edge scatter-add
    {
        long long total = (long long)e * 16;
        int threads = 256;
        long long blocks = (total + threads - 1) / threads;
        k3_scatter<<<(unsigned)blocks, threads>>>(ei, out, e);
    }
    // K4: finalize
    {
        int total = n * (D / 4);
        int threads = 256;
        int blocks = (total + threads - 1) / threads;
        k4_final<<<blocks, threads>>>(out, b, n);
    }
}

// round 3
// speedup vs baseline: 1.0911x; 1.0911x over previous
#include <cuda_runtime.h>
#include <cuda_bf16.h>
#include <cstdint>

// GCNConv forward:
//   out[i] = dis[i] * ( sum_{(r->i) in E} dis[r]*xw[r] + dis[i]*xw[i] ) + b
// where xw = x @ W, dis = rsqrt(deg), deg[i] = 1 (self loop) + #edges into i.
//
// Inputs (metadata order): x[f32 N*64], edge_index[int32 2*E], W[f32 64*64],
// b[f32 64]. Output: f32 N*64.

#define MAXN 100000
#define D 64

__device__ float  g_deg[MAXN];                      // edge-count only (self loop added later)
__device__ float4 g_sxw4[(size_t)MAXN * (D / 4)];   // dis[r]*(x@W)[r], 16B aligned

// ---------------------------------------------------------------------------
// K1: degree accumulation over edge targets, 4 edges per thread
// ---------------------------------------------------------------------------
__global__ void k1_degree(const int* __restrict__ ei, int e_cnt)
{
    int t = blockIdx.x * blockDim.x + threadIdx.x;
    int base = t * 4;
    if (base >= e_cnt) return;
    const int* col = ei + e_cnt;
    if (base + 3 < e_cnt) {
        int4 c = ((const int4*)col)[t];
        atomicAdd(&g_deg[c.x], 1.0f);
        atomicAdd(&g_deg[c.y], 1.0f);
        atomicAdd(&g_deg[c.z], 1.0f);
        atomicAdd(&g_deg[c.w], 1.0f);
    } else {
        for (int i = base; i < e_cnt; i++) atomicAdd(&g_deg[col[i]], 1.0f);
    }
}

// ---------------------------------------------------------------------------
// K2: sxw = rsqrt(deg+1) * (x @ W), packed f32x2 FMA (Blackwell FFMA2).
//     W staged in shared (16 KB), 16 rows/block, 256 threads = (row, 4-col grp).
// ---------------------------------------------------------------------------
#define GEMM_ROWS 16
__global__ __launch_bounds__(256) void k2_gemm(const float* __restrict__ x,
                                               const float* __restrict__ W,
                                               int n)
{
    __shared__ float Ws[D * D];
    __shared__ float xs[GEMM_ROWS][D];

    int tid = threadIdx.x;

    const float4* W4 = (const float4*)W;
    float4* Ws4 = (float4*)Ws;
#pragma unroll
    for (int i = 0; i < 4; i++) Ws4[tid + i * 256] = W4[tid + i * 256];

    int row0 = blockIdx.x * GEMM_ROWS;
    {
        int r = tid >> 4;
        int l = tid & 15;
        int gr = row0 + r;
        float4 v = make_float4(0.f, 0.f, 0.f, 0.f);
        if (gr < n) v = ((const float4*)(x + (size_t)gr * D))[l];
        ((float4*)&xs[r][0])[l] = v;
    }
    __syncthreads();

    int r  = tid >> 4;
    int c4 = (tid & 15) * 4;

    unsigned long long s01 = 0, s23 = 0;   // two packed f32x2 accumulators
#pragma unroll
    for (int k = 0; k < D; k++) {
        float xv = xs[r][k];
        unsigned long long xx;
        asm("mov.b64 %0, {%1, %1};" : "=l"(xx) : "f"(xv));
        ulonglong2 w = *(const ulonglong2*)(Ws + k * D + c4);  // {w0,w1},{w2,w3} packed
        asm("fma.rn.f32x2 %0, %1, %2, %0;" : "+l"(s01) : "l"(xx), "l"(w.x));
        asm("fma.rn.f32x2 %0, %1, %2, %0;" : "+l"(s23) : "l"(xx), "l"(w.y));
    }

    int gr = row0 + r;
    if (gr < n) {
        float s0, s1, s2, s3;
        asm("mov.b64 {%0, %1}, %2;" : "=f"(s0), "=f"(s1) : "l"(s01));
        asm("mov.b64 {%0, %1}, %2;" : "=f"(s2), "=f"(s3) : "l"(s23));
        float dis = rsqrtf(g_deg[gr] + 1.0f);   // +1 = self loop
        g_sxw4[(size_t)gr * (D / 4) + (tid & 15)] =
            make_float4(s0 * dis, s1 * dis, s2 * dis, s3 * dis);
    }
}

// ---------------------------------------------------------------------------
// K3: edge scatter — acc[col] += sxw[row].  16 threads x 4 edges per thread:
//     int4 index loads, 4 independent float4 gathers, 4 red.global.add.v4.f32
//     (MLP=4 to hide L2 latency).
// ---------------------------------------------------------------------------
__global__ __launch_bounds__(256) void k3_scatter(const int* __restrict__ ei,
                                                  float* __restrict__ acc, int e_cnt)
{
    int t = blockIdx.x * blockDim.x + threadIdx.x;
    int p = t >> 4;                 // quad-of-edges index
    int lane = t & 15;
    int base = p * 4;
    if (base >= e_cnt) return;

    if (base + 3 < e_cnt) {
        int4 rr = ((const int4*)ei)[p];
        int4 cc = ((const int4*)(ei + e_cnt))[p];

        float4 v0 = g_sxw4[(size_t)rr.x * (D / 4) + lane];
        float4 v1 = g_sxw4[(size_t)rr.y * (D / 4) + lane];
        float4 v2 = g_sxw4[(size_t)rr.z * (D / 4) + lane];
        float4 v3 = g_sxw4[(size_t)rr.w * (D / 4) + lane];

        float* d0 = acc + (size_t)cc.x * D + lane * 4;
        float* d1 = acc + (size_t)cc.y * D + lane * 4;
        float* d2 = acc + (size_t)cc.z * D + lane * 4;
        float* d3 = acc + (size_t)cc.w * D + lane * 4;
        asm volatile("red.global.add.v4.f32 [%0], {%1, %2, %3, %4};"
                     :: "l"(d0), "f"(v0.x), "f"(v0.y), "f"(v0.z), "f"(v0.w) : "memory");
        asm volatile("red.global.add.v4.f32 [%0], {%1, %2, %3, %4};"
                     :: "l"(d1), "f"(v1.x), "f"(v1.y), "f"(v1.z), "f"(v1.w) : "memory");
        asm volatile("red.global.add.v4.f32 [%0], {%1, %2, %3, %4};"
                     :: "l"(d2), "f"(v2.x), "f"(v2.y), "f"(v2.z), "f"(v2.w) : "memory");
        asm volatile("red.global.add.v4.f32 [%0], {%1, %2, %3, %4};"
                     :: "l"(d3), "f"(v3.x), "f"(v3.y), "f"(v3.z), "f"(v3.w) : "memory");
    } else {
        for (int e0 = base; e0 < e_cnt; e0++) {
            int r = ei[e0];
            int c = ei[e_cnt + e0];
            float4 v = g_sxw4[(size_t)r * (D / 4) + lane];
            float* dst = acc + (size_t)c * D + lane * 4;
            asm volatile("red.global.add.v4.f32 [%0], {%1, %2, %3, %4};"
                         :: "l"(dst), "f"(v.x), "f"(v.y), "f"(v.z), "f"(v.w) : "memory");
        }
    }
}

// ---------------------------------------------------------------------------
// K4: finalize — out = dis * (acc + sxw) + b   (in-place on d_out)
// ---------------------------------------------------------------------------
__global__ void k4_final(float* __restrict__ out, const float* __restrict__ b,
                         int n)
{
    int t = blockIdx.x * blockDim.x + threadIdx.x;
    if (t >= n * (D / 4)) return;
    int node = t >> 4;
    int c4 = (t & 15) * 4;

    float dis = rsqrtf(g_deg[node] + 1.0f);
    float4 a = ((float4*)out)[t];
    float4 s = g_sxw4[t];
    float4 bb = *(const float4*)(b + c4);
    float4 o;
    o.x = dis * (a.x + s.x) + bb.x;
    o.y = dis * (a.y + s.y) + bb.y;
    o.z = dis * (a.z + s.z) + bb.z;
    o.w = dis * (a.w + s.w) + bb.w;
    ((float4*)out)[t] = o;
}

// ---------------------------------------------------------------------------
extern "C" void kernel_launch(void* const* d_in, const int* in_sizes, int n_in,
                              void* d_out, int out_size)
{
    const float* x  = (const float*)d_in[0];
    const int*   ei = (const int*)d_in[1];     // int32 (jax default, no x64)
    const float* W  = (const float*)d_in[2];
    const float* b  = (const float*)d_in[3];
    float* out = (float*)d_out;

    int n = in_sizes[0] / D;       // 100000
    int e = in_sizes[1] / 2;       // 1600000

    float* deg;
    cudaGetSymbolAddress((void**)&deg, g_deg);

    // init: zero accumulator (d_out) and deg
    cudaMemsetAsync(out, 0, (size_t)n * D * sizeof(float), 0);
    cudaMemsetAsync(deg, 0, (size_t)n * sizeof(float), 0);

    // K1: degree scatter (4 edges/thread)
    {
        int threads = 256;
        int quads = (e + 3) / 4;
        int blocks = (quads + threads - 1) / threads;
        k1_degree<<<blocks, threads>>>(ei, e);
    }
    // K2: sxw = rsqrt(deg+1) * (x @ W)
    {
        int blocks = (n + GEMM_ROWS - 1) / GEMM_ROWS;
        k2_gemm<<<blocks, 256>>>(x, W, n);
    }
    // K3: edge scatter-add, 4 edges per 16-thread group
    {
        long long quads = (e + 3) / 4;
        long long total = quads * 16;
        int threads = 256;
        long long blocks = (total + threads - 1) / threads;
        k3_scatter<<<(unsigned)blocks, threads>>>(ei, out, e);
    }
    // K4: finalize
    {
        int total = n * (D / 4);
        int threads = 256;
        int blocks = (total + threads - 1) / threads;
        k4_final<<<blocks, threads>>>(out, b, n);
    }
}